// round 2
// baseline (speedup 1.0000x reference)
#include <cuda_runtime.h>
#include <cuda_bf16.h>

// Problem shape (fixed by the dataset)
#define BATCH 128
#define SEQLEN 1024
#define TAG 128

// Scratch (allocation-free rule: __device__ globals)
__device__ float g_logZ[BATCH];
__device__ float g_score[BATCH];

// ---------------- packed f32x2 helpers (Blackwell FFMA2) ----------------
__device__ __forceinline__ unsigned long long pack_f32x2(float lo, float hi) {
    unsigned long long r;
    asm("mov.b64 %0, {%1, %2};" : "=l"(r) : "f"(lo), "f"(hi));
    return r;
}
__device__ __forceinline__ void unpack_f32x2(float& lo, float& hi, unsigned long long v) {
    asm("mov.b64 {%0, %1}, %2;" : "=f"(lo), "=f"(hi) : "l"(v));
}
__device__ __forceinline__ unsigned long long fma2(unsigned long long a,
                                                   unsigned long long b,
                                                   unsigned long long c) {
    unsigned long long d;
    asm("fma.rn.f32x2 %0, %1, %2, %3;" : "=l"(d) : "l"(a), "l"(b), "l"(c));
    return d;
}
__device__ __forceinline__ unsigned long long add2(unsigned long long a,
                                                   unsigned long long b) {
    unsigned long long d;
    asm("add.rn.f32x2 %0, %1, %2;" : "=l"(d) : "l"(a), "l"(b));
    return d;
}

// ---------------- one recurrence step (templated for compile-time ring/buf) ---
// SLOT: prefetch ring slot for this step's y_pred/mask row. BUF: p double-buffer.
template <int SLOT, int BUF>
__device__ __forceinline__ void crf_step(
    int i, int t, float& pre, float& shift,
    float (&ypr)[4], float (&mr)[4],
    const float* __restrict__ yprow, const float* __restrict__ mrow,
    float colmax, const unsigned long long (&ea2)[64],
    float (*pbuf)[TAG], float* sbroad)
{
    // publish p (computed against the shift broadcast last step) and the
    // representative lane value for the *next* step's shift — one barrier.
    float p = __expf(pre - shift);
    pbuf[BUF][t] = p;
    if (t == 0) sbroad[BUF] = pre;
    __syncthreads();
    float nshift = sbroad[BUF] + 32.0f;

    // prefetch row i+4 into this slot (consumed 4 steps from now)
    float yp_n = 0.0f, m_n = 1.0f;
    if (i + 4 < SEQLEN) {
        yp_n = __ldg(yprow + (i + 4) * TAG);
        m_n  = __ldg(mrow + (i + 4));
    }

    // 128-wide dot: s_t = sum_u p[u] * EA[u][t], EA column resident in registers.
    unsigned long long acc0 = 0ull, acc1 = 0ull, acc2 = 0ull, acc3 = 0ull;
    const ulonglong2* pp = reinterpret_cast<const ulonglong2*>(&pbuf[BUF][0]);
#pragma unroll
    for (int k = 0; k < 16; k++) {
        ulonglong2 v0 = pp[2 * k];
        ulonglong2 v1 = pp[2 * k + 1];
        acc0 = fma2(v0.x, ea2[4 * k + 0], acc0);
        acc1 = fma2(v0.y, ea2[4 * k + 1], acc1);
        acc2 = fma2(v1.x, ea2[4 * k + 2], acc2);
        acc3 = fma2(v1.y, ea2[4 * k + 3], acc3);
    }
    unsigned long long accA = add2(add2(acc0, acc1), add2(acc2, acc3));
    float slo, shi;
    unpack_f32x2(slo, shi, accA);
    float s = slo + shi;

    float yp = ypr[SLOT];
    float m  = mr[SLOT];
    float lz = shift + colmax + __logf(s);
    pre = m * (lz + yp) + (1.0f - m) * pre;
    shift = nshift;
    ypr[SLOT] = yp_n;
    mr[SLOT]  = m_n;
}

// ---------------- forward (log_Z) kernel: 1 CTA per batch ----------------
__global__ void __launch_bounds__(TAG, 1)
crf_forward_kernel(const float* __restrict__ y_pred,
                   const float* __restrict__ mask,
                   const float* __restrict__ A)
{
    const int b = blockIdx.x;
    const int t = threadIdx.x;

    __shared__ __align__(16) float pbuf[2][TAG];
    __shared__ float sbroad[2];

    // ---- load EA column t into registers; compute column max of A ----
    // A[u*TAG + t]: for fixed u, lanes read consecutive floats -> coalesced.
    float colmax = -1e30f;
#pragma unroll 8
    for (int u = 0; u < TAG; u++) {
        colmax = fmaxf(colmax, __ldg(A + u * TAG + t));
    }
    unsigned long long ea2[64];
#pragma unroll
    for (int k = 0; k < 64; k++) {
        float e0 = __expf(__ldg(A + (2 * k)     * TAG + t) - colmax);
        float e1 = __expf(__ldg(A + (2 * k + 1) * TAG + t) - colmax);
        ea2[k] = pack_f32x2(e0, e1);
    }

    const float* yprow = y_pred + (size_t)b * SEQLEN * TAG + t;  // row i at yprow[i*TAG]
    const float* mrow  = mask + (size_t)b * SEQLEN;

    // ---- init: pre = y_pred[b, 0, :]; shift = pre[0] + 32 ----
    float pre = __ldg(yprow);
    if (t == 0) sbroad[0] = pre;
    __syncthreads();
    float shift = sbroad[0] + 32.0f;

    // prefetch rows 1..4
    float ypr[4], mr[4];
#pragma unroll
    for (int j = 0; j < 4; j++) {
        ypr[j] = __ldg(yprow + (1 + j) * TAG);
        mr[j]  = __ldg(mrow + (1 + j));
    }

    // ---- main scan: steps i = 1 .. SEQLEN-1 (1023 steps = 255*4 + 3) ----
    int i = 1;
    for (; i + 3 < SEQLEN; i += 4) {
        crf_step<0, 1>(i,     t, pre, shift, ypr, mr, yprow, mrow, colmax, ea2, pbuf, sbroad);
        crf_step<1, 0>(i + 1, t, pre, shift, ypr, mr, yprow, mrow, colmax, ea2, pbuf, sbroad);
        crf_step<2, 1>(i + 2, t, pre, shift, ypr, mr, yprow, mrow, colmax, ea2, pbuf, sbroad);
        crf_step<3, 0>(i + 3, t, pre, shift, ypr, mr, yprow, mrow, colmax, ea2, pbuf, sbroad);
    }
    // remainder: i = 1021, 1022, 1023
    crf_step<0, 1>(i,     t, pre, shift, ypr, mr, yprow, mrow, colmax, ea2, pbuf, sbroad);
    crf_step<1, 0>(i + 1, t, pre, shift, ypr, mr, yprow, mrow, colmax, ea2, pbuf, sbroad);
    crf_step<2, 1>(i + 2, t, pre, shift, ypr, mr, yprow, mrow, colmax, ea2, pbuf, sbroad);

    // ---- final logsumexp over tags ----
    if (t == 0) sbroad[0] = pre;
    __syncthreads();
    float sf = sbroad[0] + 32.0f;
    pbuf[0][t] = __expf(pre - sf);
    __syncthreads();
    if (t < 32) {
        float v = pbuf[0][t] + pbuf[0][t + 32] + pbuf[0][t + 64] + pbuf[0][t + 96];
#pragma unroll
        for (int o = 16; o > 0; o >>= 1)
            v += __shfl_xor_sync(0xffffffffu, v, o);
        if (t == 0) g_logZ[b] = sf + __logf(v);
    }
}

// ---------------- score kernel: 1 CTA per batch ----------------
// y_true arrives as int32 under JAX's default x64-disabled config; handle a
// genuine little-endian int64 layout too by runtime detection (odd 32-bit
// words of the first 128 entries all zero <=> int64, since tags are 0..127).
__global__ void __launch_bounds__(128, 1)
crf_score_kernel(const float* __restrict__ y_pred,
                 const int* __restrict__ y_true32,
                 const float* __restrict__ mask,
                 const float* __restrict__ A)
{
    const int b = blockIdx.x;
    const int t = threadIdx.x;

    // dtype detection (same verdict in every block; deterministic)
    __shared__ int s_is64;
    if (t == 0) {
        int all_zero = 1;
        for (int j = 0; j < 128; j++) {
            if (y_true32[2 * j + 1] != 0) { all_zero = 0; break; }
        }
        s_is64 = all_zero;
    }
    __syncthreads();
    const int stride = s_is64 ? 2 : 1;
    const int* yt = y_true32 + (size_t)b * SEQLEN * stride;

    const float* mrow = mask + (size_t)b * SEQLEN;
    const float* yprow = y_pred + (size_t)b * SEQLEN * TAG;

    float acc = 0.0f;
    for (int s = t; s < SEQLEN; s += 128) {
        int tag = yt[s * stride] & (TAG - 1);   // tags are 0..127; mask is safety net
        float m = mrow[s];
        acc += yprow[(size_t)s * TAG + tag] * m;
        if (s + 1 < SEQLEN) {
            int tag2 = yt[(s + 1) * stride] & (TAG - 1);
            float m2 = mrow[s + 1];
            acc += A[tag * TAG + tag2] * m * m2;
        }
    }
    __shared__ float red[128];
    red[t] = acc;
    __syncthreads();
    if (t < 32) {
        float v = red[t] + red[t + 32] + red[t + 64] + red[t + 96];
#pragma unroll
        for (int o = 16; o > 0; o >>= 1)
            v += __shfl_xor_sync(0xffffffffu, v, o);
        if (t == 0) g_score[b] = v;
    }
}

// ---------------- final mean kernel ----------------
__global__ void __launch_bounds__(128, 1)
crf_final_kernel(float* __restrict__ out)
{
    const int t = threadIdx.x;
    float v = g_logZ[t] - g_score[t];
    __shared__ float red[128];
    red[t] = v;
    __syncthreads();
    if (t < 32) {
        float s = red[t] + red[t + 32] + red[t + 64] + red[t + 96];
#pragma unroll
        for (int o = 16; o > 0; o >>= 1)
            s += __shfl_xor_sync(0xffffffffu, s, o);
        if (t == 0) out[0] = s * (1.0f / (float)BATCH);
    }
}

// ---------------- launch ----------------
extern "C" void kernel_launch(void* const* d_in, const int* in_sizes, int n_in,
                              void* d_out, int out_size)
{
    // Identify inputs by element count:
    //   y_pred: BATCH*SEQLEN*TAG, A: TAG*TAG, y_true & mask: BATCH*SEQLEN
    //   (y_true precedes mask in metadata/dict order).
    const float* y_pred = nullptr;
    const float* A = nullptr;
    const int* y_true = nullptr;
    const float* mask = nullptr;
    for (int i = 0; i < n_in; i++) {
        long long sz = in_sizes[i];
        if (sz == (long long)BATCH * SEQLEN * TAG) {
            y_pred = (const float*)d_in[i];
        } else if (sz == (long long)TAG * TAG) {
            A = (const float*)d_in[i];
        } else if (sz == (long long)BATCH * SEQLEN) {
            if (!y_true) y_true = (const int*)d_in[i];
            else mask = (const float*)d_in[i];
        }
    }

    crf_forward_kernel<<<BATCH, TAG>>>(y_pred, mask, A);
    crf_score_kernel<<<BATCH, 128>>>(y_pred, y_true, mask, A);
    crf_final_kernel<<<1, 128>>>((float*)d_out);
}

// round 3
// speedup vs baseline: 1.1859x; 1.1859x over previous
#include <cuda_runtime.h>
#include <cuda_bf16.h>

// Problem shape (fixed by the dataset)
#define BATCH 128
#define SEQLEN 1024
#define TAG 128

// Scratch (allocation-free rule: __device__ globals)
__device__ float g_logZ[BATCH];
__device__ float g_score[BATCH];

// ---------------- packed f32x2 helpers (Blackwell FFMA2) ----------------
__device__ __forceinline__ unsigned long long pack_f32x2(float lo, float hi) {
    unsigned long long r;
    asm("mov.b64 %0, {%1, %2};" : "=l"(r) : "f"(lo), "f"(hi));
    return r;
}
__device__ __forceinline__ void unpack_f32x2(float& lo, float& hi, unsigned long long v) {
    asm("mov.b64 {%0, %1}, %2;" : "=f"(lo), "=f"(hi) : "l"(v));
}
__device__ __forceinline__ unsigned long long fma2(unsigned long long a,
                                                   unsigned long long b,
                                                   unsigned long long c) {
    unsigned long long d;
    asm("fma.rn.f32x2 %0, %1, %2, %3;" : "=l"(d) : "l"(a), "l"(b), "l"(c));
    return d;
}
__device__ __forceinline__ unsigned long long add2(unsigned long long a,
                                                   unsigned long long b) {
    unsigned long long d;
    asm("add.rn.f32x2 %0, %1, %2;" : "=l"(d) : "l"(a), "l"(b));
    return d;
}

// ---------------- one exp-domain recurrence step --------------------------
// SLOT: prefetch ring slot for this step's e^{y_pred}/mask. BUF: alpha buffer.
// alpha is the scaled forward variable; kacc accumulates the power-of-2
// renormalization exponent (identical on all threads: derived from broadcast).
template <int SLOT, int BUF>
__device__ __forceinline__ void crf_step(
    int i, int t, float& alpha, int& kacc,
    float (&eyp)[4], float (&mr)[4],
    const float* __restrict__ yprow, const float* __restrict__ mrow,
    const unsigned long long (&ea2)[64],
    float (*pbuf)[TAG], float* sbroad)
{
    // publish alpha and the representative lane value — one barrier.
    pbuf[BUF][t] = alpha;
    if (t == 0) sbroad[BUF] = alpha;
    __syncthreads();

    // power-of-2 renormalization factor from the representative's exponent
    // (pure ALU; exact in fp32). invc = 2^(127 - kb), scaling repr into [1,2).
    float repr = sbroad[BUF];
    int kb = (__float_as_int(repr) >> 23) & 0xff;
    float invc = __int_as_float((254 - kb) << 23);
    kacc += 127 - kb;

    // prefetch row i+4 into this slot (consumed 4 steps from now); the exp is
    // computed here, entirely off the recurrence's serial chain.
    float eyp_n = 0.0f, m_n = 1.0f;
    if (i + 4 < SEQLEN) {
        eyp_n = __expf(__ldg(yprow + (i + 4) * TAG));
        m_n   = __ldg(mrow + (i + 4));
    }

    // 128-wide dot: s_t = sum_u alpha[u] * e^{A[u][t]}, EA resident in regs.
    unsigned long long acc0 = 0ull, acc1 = 0ull, acc2 = 0ull, acc3 = 0ull;
    const ulonglong2* pp = reinterpret_cast<const ulonglong2*>(&pbuf[BUF][0]);
#pragma unroll
    for (int k = 0; k < 16; k++) {
        ulonglong2 v0 = pp[2 * k];
        ulonglong2 v1 = pp[2 * k + 1];
        acc0 = fma2(v0.x, ea2[4 * k + 0], acc0);
        acc1 = fma2(v0.y, ea2[4 * k + 1], acc1);
        acc2 = fma2(v1.x, ea2[4 * k + 2], acc2);
        acc3 = fma2(v1.y, ea2[4 * k + 3], acc3);
    }
    unsigned long long accA = add2(add2(acc0, acc1), add2(acc2, acc3));
    float slo, shi;
    unpack_f32x2(slo, shi, accA);
    float s = slo + shi;

    // masked update (mask is {0,1}); both branches carry the same invc so the
    // accumulated kacc stays consistent.
    float cand = s * eyp[SLOT] * invc;
    alpha = (mr[SLOT] > 0.5f) ? cand : alpha * invc;
    eyp[SLOT] = eyp_n;
    mr[SLOT]  = m_n;
}

// ---------------- forward (log_Z) kernel: 1 CTA per batch ----------------
__global__ void __launch_bounds__(TAG, 1)
crf_forward_kernel(const float* __restrict__ y_pred,
                   const float* __restrict__ mask,
                   const float* __restrict__ A)
{
    const int b = blockIdx.x;
    const int t = threadIdx.x;

    __shared__ __align__(16) float pbuf[2][TAG];
    __shared__ float sbroad[2];

    // ---- load e^{A} column t into registers (A in [-0.1,0.1]: no shift) ----
    unsigned long long ea2[64];
#pragma unroll
    for (int k = 0; k < 64; k++) {
        float e0 = __expf(__ldg(A + (2 * k)     * TAG + t));
        float e1 = __expf(__ldg(A + (2 * k + 1) * TAG + t));
        ea2[k] = pack_f32x2(e0, e1);
    }

    const float* yprow = y_pred + (size_t)b * SEQLEN * TAG + t;  // row i at yprow[i*TAG]
    const float* mrow  = mask + (size_t)b * SEQLEN;

    // ---- init: alpha = e^{y_pred[b,0,:]} ----
    float alpha = __expf(__ldg(yprow));
    int kacc = 0;

    // prefetch rows 1..4 (with exp applied)
    float eyp[4], mr[4];
#pragma unroll
    for (int j = 0; j < 4; j++) {
        eyp[j] = __expf(__ldg(yprow + (1 + j) * TAG));
        mr[j]  = __ldg(mrow + (1 + j));
    }

    // ---- main scan: steps i = 1 .. SEQLEN-1 (1023 steps = 255*4 + 3) ----
    int i = 1;
    for (; i + 3 < SEQLEN; i += 4) {
        crf_step<0, 1>(i,     t, alpha, kacc, eyp, mr, yprow, mrow, ea2, pbuf, sbroad);
        crf_step<1, 0>(i + 1, t, alpha, kacc, eyp, mr, yprow, mrow, ea2, pbuf, sbroad);
        crf_step<2, 1>(i + 2, t, alpha, kacc, eyp, mr, yprow, mrow, ea2, pbuf, sbroad);
        crf_step<3, 0>(i + 3, t, alpha, kacc, eyp, mr, yprow, mrow, ea2, pbuf, sbroad);
    }
    // remainder: i = 1021, 1022, 1023
    crf_step<0, 1>(i,     t, alpha, kacc, eyp, mr, yprow, mrow, ea2, pbuf, sbroad);
    crf_step<1, 0>(i + 1, t, alpha, kacc, eyp, mr, yprow, mrow, ea2, pbuf, sbroad);
    crf_step<2, 1>(i + 2, t, alpha, kacc, eyp, mr, yprow, mrow, ea2, pbuf, sbroad);

    // ---- final: logZ = log(sum_t alpha) - kacc*ln2 ----
    pbuf[0][t] = alpha;
    __syncthreads();
    if (t < 32) {
        float v = pbuf[0][t] + pbuf[0][t + 32] + pbuf[0][t + 64] + pbuf[0][t + 96];
#pragma unroll
        for (int o = 16; o > 0; o >>= 1)
            v += __shfl_xor_sync(0xffffffffu, v, o);
        if (t == 0)
            g_logZ[b] = logf(v) - (float)kacc * 0.69314718055994530942f;
    }
}

// ---------------- score kernel: 1 CTA per batch ----------------
// y_true arrives as int32 under JAX's default x64-disabled config; handle a
// genuine little-endian int64 layout too by runtime detection (odd 32-bit
// words of the first 128 entries all zero <=> int64, since tags are 0..127).
__global__ void __launch_bounds__(128, 1)
crf_score_kernel(const float* __restrict__ y_pred,
                 const int* __restrict__ y_true32,
                 const float* __restrict__ mask,
                 const float* __restrict__ A)
{
    const int b = blockIdx.x;
    const int t = threadIdx.x;

    // dtype detection (same verdict in every block; deterministic)
    __shared__ int s_is64;
    if (t == 0) {
        int all_zero = 1;
        for (int j = 0; j < 128; j++) {
            if (y_true32[2 * j + 1] != 0) { all_zero = 0; break; }
        }
        s_is64 = all_zero;
    }
    __syncthreads();
    const int stride = s_is64 ? 2 : 1;
    const int* yt = y_true32 + (size_t)b * SEQLEN * stride;

    const float* mrow = mask + (size_t)b * SEQLEN;
    const float* yprow = y_pred + (size_t)b * SEQLEN * TAG;

    float acc = 0.0f;
    for (int s = t; s < SEQLEN; s += 128) {
        int tag = yt[s * stride] & (TAG - 1);   // tags are 0..127; mask is safety net
        float m = mrow[s];
        acc += yprow[(size_t)s * TAG + tag] * m;
        if (s + 1 < SEQLEN) {
            int tag2 = yt[(s + 1) * stride] & (TAG - 1);
            float m2 = mrow[s + 1];
            acc += A[tag * TAG + tag2] * m * m2;
        }
    }
    __shared__ float red[128];
    red[t] = acc;
    __syncthreads();
    if (t < 32) {
        float v = red[t] + red[t + 32] + red[t + 64] + red[t + 96];
#pragma unroll
        for (int o = 16; o > 0; o >>= 1)
            v += __shfl_xor_sync(0xffffffffu, v, o);
        if (t == 0) g_score[b] = v;
    }
}

// ---------------- final mean kernel ----------------
__global__ void __launch_bounds__(128, 1)
crf_final_kernel(float* __restrict__ out)
{
    const int t = threadIdx.x;
    float v = g_logZ[t] - g_score[t];
    __shared__ float red[128];
    red[t] = v;
    __syncthreads();
    if (t < 32) {
        float s = red[t] + red[t + 32] + red[t + 64] + red[t + 96];
#pragma unroll
        for (int o = 16; o > 0; o >>= 1)
            s += __shfl_xor_sync(0xffffffffu, s, o);
        if (t == 0) out[0] = s * (1.0f / (float)BATCH);
    }
}

// ---------------- launch ----------------
extern "C" void kernel_launch(void* const* d_in, const int* in_sizes, int n_in,
                              void* d_out, int out_size)
{
    // Identify inputs by element count:
    //   y_pred: BATCH*SEQLEN*TAG, A: TAG*TAG, y_true & mask: BATCH*SEQLEN
    //   (y_true precedes mask in metadata/dict order).
    const float* y_pred = nullptr;
    const float* A = nullptr;
    const int* y_true = nullptr;
    const float* mask = nullptr;
    for (int i = 0; i < n_in; i++) {
        long long sz = in_sizes[i];
        if (sz == (long long)BATCH * SEQLEN * TAG) {
            y_pred = (const float*)d_in[i];
        } else if (sz == (long long)TAG * TAG) {
            A = (const float*)d_in[i];
        } else if (sz == (long long)BATCH * SEQLEN) {
            if (!y_true) y_true = (const int*)d_in[i];
            else mask = (const float*)d_in[i];
        }
    }

    crf_forward_kernel<<<BATCH, TAG>>>(y_pred, mask, A);
    crf_score_kernel<<<BATCH, 128>>>(y_pred, y_true, mask, A);
    crf_final_kernel<<<1, 128>>>((float*)d_out);
}